// round 14
// baseline (speedup 1.0000x reference)
#include <cuda_runtime.h>
#include <cuda_fp16.h>
#include <cstdint>

#define C 64
#define MAXN 50000
#define MAXE 800000

// ---------------- device scratch (static: no allocation allowed) ----------------
__device__ float  g_v[MAXN * C];
__device__ __half g_hQ1[MAXN * C];
__device__ __half g_hK1[MAXN * C];
__device__ float4 g_pos4[MAXN];
__device__ float  g_num[MAXN * C];
__device__ float  g_den[MAXN * C];
__device__ float g_Mq_t[C * C];
__device__ float g_Mk_t[C * C];
__device__ float g_Win_t[C * C];
__device__ float g_Wlin_t[C * C];
__device__ float g_w2a_t[C * C];
__device__ float g_w2p_t[C * C];
__device__ float g_Wout_t[C * C];
__device__ float g_delta0[C];
__device__ float g_fWin[4096];
__device__ float g_fWlin[4096];
__device__ float g_fMq[4096];
__device__ float g_fMk[4096];
__device__ float g_fW2a[4096];
__device__ float g_fWout[4096];
// fp16 B fragments for edge MLP-2 GEMMs: [(kt*8+nt)*32+lane] -> uint2 {b0,b1}
__device__ uint2 g_hW2a[1024];
__device__ uint2 g_hW2p[1024];

__device__ __forceinline__ unsigned f2tf32(float f) {
    unsigned r;
    asm("cvt.rna.tf32.f32 %0, %1;" : "=r"(r) : "f"(f));
    return r;
}
__device__ __forceinline__ unsigned pack_h2(float a, float b) {
    __half2 h = __floats2half2_rn(a, b);
    return *reinterpret_cast<unsigned*>(&h);
}

#define MMA_TF32(d, a, b0, b1)                                               \
    asm volatile("mma.sync.aligned.m16n8k8.row.col.f32.tf32.tf32.f32 "       \
                 "{%0,%1,%2,%3}, {%4,%5,%6,%7}, {%8,%9}, {%0,%1,%2,%3};"     \
                 : "+f"(d[0]), "+f"(d[1]), "+f"(d[2]), "+f"(d[3])            \
                 : "r"(a[0]), "r"(a[1]), "r"(a[2]), "r"(a[3]),               \
                   "r"(b0), "r"(b1))

#define MMA_F16(d, a, b0, b1)                                                \
    asm volatile("mma.sync.aligned.m16n8k16.row.col.f32.f16.f16.f32 "        \
                 "{%0,%1,%2,%3}, {%4,%5,%6,%7}, {%8,%9}, {%0,%1,%2,%3};"     \
                 : "+f"(d[0]), "+f"(d[1]), "+f"(d[2]), "+f"(d[3])            \
                 : "r"(a[0]), "r"(a[1]), "r"(a[2]), "r"(a[3]),               \
                   "r"(b0), "r"(b1))

#define RED_V4(ptr, v)                                                       \
    asm volatile("red.global.add.v4.f32 [%0], {%1,%2,%3,%4};"                \
                 :: "l"(ptr), "f"((v).x), "f"((v).y), "f"((v).z), "f"((v).w) \
                 : "memory")

#define HBAR(id)                                                             \
    asm volatile("bar.sync %0, 128;" :: "r"(id) : "memory")

__device__ __forceinline__ void ldsm_x4(unsigned& r0, unsigned& r1,
                                        unsigned& r2, unsigned& r3, unsigned addr) {
    asm volatile("ldmatrix.sync.aligned.m8n8.x4.shared.b16 {%0,%1,%2,%3}, [%4];"
                 : "=r"(r0), "=r"(r1), "=r"(r2), "=r"(r3) : "r"(addr));
}

// ---------------- K0: weight prep ------------------------------------------------
__global__ void prep_kernel(const float* __restrict__ att_w1,
                            const float* __restrict__ W_dst,
                            const float* __restrict__ W_src,
                            const float* __restrict__ W_in,
                            const float* __restrict__ W_lin,
                            const float* __restrict__ att_w2,
                            const float* __restrict__ pos_w2,
                            const float* __restrict__ W_out,
                            const float* __restrict__ pos_b1,
                            const float* __restrict__ pos_b2)
{
    __shared__ float s_a[C * C];
    __shared__ float s_d[C * C];
    __shared__ float s_s[C * C];
    int tid = threadIdx.x;
    for (int t = tid; t < C * C; t += blockDim.x) {
        s_a[t] = att_w1[t];
        s_d[t] = W_dst[t];
        s_s[t] = W_src[t];
    }
    __syncthreads();
    for (int idx = tid; idx < C * C; idx += blockDim.x) {
        int t = idx >> 6, j = idx & 63;
        float aq = 0.f, ak = 0.f;
        #pragma unroll 8
        for (int u = 0; u < C; u++) {
            float a = s_a[t * C + u];
            aq = fmaf(a, s_d[u * C + j], aq);
            ak = fmaf(a, s_s[u * C + j], ak);
        }
        g_Mq_t[j * C + t] = aq;
        g_Mk_t[j * C + t] = ak;
    }
    for (int idx = tid; idx < C * C; idx += blockDim.x) {
        int cc = idx >> 6, j = idx & 63;
        g_Win_t[j * C + cc]  = W_in[idx];
        g_Wlin_t[j * C + cc] = W_lin[idx];
        g_w2a_t[j * C + cc]  = att_w2[idx];
        g_w2p_t[j * C + cc]  = pos_w2[idx];
        g_Wout_t[j * C + cc] = W_out[idx];
    }
    if (tid < C) {
        float acc = pos_b2[tid];
        #pragma unroll 8
        for (int j = 0; j < C; j++)
            acc = fmaf(fmaxf(pos_b1[j], 0.f), pos_w2[tid * C + j], acc);
        g_delta0[tid] = fmaxf(acc, 0.f);
    }
    __syncthreads();
    for (int t = tid; t < 2048; t += blockDim.x) {
        int kt   = t >> 8;
        int nt   = (t >> 5) & 7;
        int lane = t & 31;
        int kr = kt * 8 + (lane & 3);
        int nc = nt * 8 + (lane >> 2);
        int lo = kr * 64 + nc, hi = (kr + 4) * 64 + nc;
        ((float2*)g_fWin)[t]  = make_float2(__uint_as_float(f2tf32(g_Win_t[lo])),
                                            __uint_as_float(f2tf32(g_Win_t[hi])));
        ((float2*)g_fWlin)[t] = make_float2(__uint_as_float(f2tf32(g_Wlin_t[lo])),
                                            __uint_as_float(f2tf32(g_Wlin_t[hi])));
        ((float2*)g_fMq)[t]   = make_float2(__uint_as_float(f2tf32(g_Mq_t[lo])),
                                            __uint_as_float(f2tf32(g_Mq_t[hi])));
        ((float2*)g_fMk)[t]   = make_float2(__uint_as_float(f2tf32(g_Mk_t[lo])),
                                            __uint_as_float(f2tf32(g_Mk_t[hi])));
        ((float2*)g_fW2a)[t]  = make_float2(__uint_as_float(f2tf32(g_w2a_t[lo])),
                                            __uint_as_float(f2tf32(g_w2a_t[hi])));
        ((float2*)g_fWout)[t] = make_float2(__uint_as_float(f2tf32(g_Wout_t[lo])),
                                            __uint_as_float(f2tf32(g_Wout_t[hi])));
    }
    // fp16 B fragments for edge kernel (m16n8k16)
    for (int t = tid; t < 1024; t += blockDim.x) {
        int kt   = t >> 8;
        int nt   = (t >> 5) & 7;
        int lane = t & 31;
        int tig = lane & 3, gid = lane >> 2;
        int n  = nt * 8 + gid;
        int k0 = kt * 16 + tig * 2;
        uint2 ua, up;
        ua.x = pack_h2(g_w2a_t[k0 * 64 + n],       g_w2a_t[(k0 + 1) * 64 + n]);
        ua.y = pack_h2(g_w2a_t[(k0 + 8) * 64 + n], g_w2a_t[(k0 + 9) * 64 + n]);
        up.x = pack_h2(g_w2p_t[k0 * 64 + n],       g_w2p_t[(k0 + 1) * 64 + n]);
        up.y = pack_h2(g_w2p_t[(k0 + 8) * 64 + n], g_w2p_t[(k0 + 9) * 64 + n]);
        g_hW2a[t] = ua;
        g_hW2p[t] = up;
    }
}

// ---------------- dummy (instrumentation spacer so ncu window hits edge_kernel) --
__global__ void spacer_kernel() {}

// ---------------- K1: node kernel — 4 fused tf32 GEMMs over 64-node tiles -------
__global__ void __launch_bounds__(256)
node_kernel(const float* __restrict__ x,
            const float* __restrict__ pos,
            const float* __restrict__ b_in,
            const float* __restrict__ att_b1,
            const float* __restrict__ att_b2,
            int n)
{
    extern __shared__ float sm[];
    float* xs = sm;
    float* hs = sm + 4352;
    float* vs = sm + 8704;
    int tid  = threadIdx.x;
    int lane = tid & 31;
    int wid  = tid >> 5;
    int base = blockIdx.x * 64;

    for (int t = tid; t < 1024; t += 256) {
        int row = t >> 4;
        int col = (t & 15) * 4;
        int node = base + row;
        float4 v4 = make_float4(0.f, 0.f, 0.f, 0.f);
        if (node < n) v4 = *(const float4*)(x + (size_t)node * C + col);
        float4 r;
        r.x = __uint_as_float(f2tf32(v4.x));
        r.y = __uint_as_float(f2tf32(v4.y));
        r.z = __uint_as_float(f2tf32(v4.z));
        r.w = __uint_as_float(f2tf32(v4.w));
        *(float4*)(xs + row * 68 + col) = r;
    }
    if (tid < 64) {
        int node = base + tid;
        if (node < n) {
            g_pos4[node] = make_float4(pos[(size_t)node * 3 + 0],
                                       pos[(size_t)node * 3 + 1],
                                       pos[(size_t)node * 3 + 2], 0.f);
        }
    }
    __syncthreads();

    int r0 = (wid & 3) * 16;
    int nh = wid >> 2;
    int n0 = nh * 32;
    int rA = lane >> 2;
    int cb = 2 * (lane & 3);
    int rowg0 = base + r0 + rA;
    int rowg1 = rowg0 + 8;
    bool ok0 = rowg0 < n, ok1 = rowg1 < n;

    {
        float acc[4][4];
        #pragma unroll
        for (int nt = 0; nt < 4; nt++) {
            int col = n0 + nt * 8 + cb;
            float b0 = b_in[col], b1 = b_in[col + 1];
            acc[nt][0] = b0; acc[nt][1] = b1; acc[nt][2] = b0; acc[nt][3] = b1;
        }
        #pragma unroll
        for (int kt = 0; kt < 8; kt++) {
            int cA = kt * 8 + (lane & 3);
            unsigned a[4];
            a[0] = __float_as_uint(xs[(r0 + rA) * 68 + cA]);
            a[1] = __float_as_uint(xs[(r0 + 8 + rA) * 68 + cA]);
            a[2] = __float_as_uint(xs[(r0 + rA) * 68 + cA + 4]);
            a[3] = __float_as_uint(xs[(r0 + 8 + rA) * 68 + cA + 4]);
            #pragma unroll
            for (int nt = 0; nt < 4; nt++) {
                float2 b = ((const float2*)g_fWin)[(kt * 8 + nh * 4 + nt) * 32 + lane];
                MMA_TF32(acc[nt], a, __float_as_uint(b.x), __float_as_uint(b.y));
            }
        }
        #pragma unroll
        for (int nt = 0; nt < 4; nt++) {
            int col = n0 + nt * 8 + cb;
            hs[(r0 + rA) * 68 + col]       = __uint_as_float(f2tf32(fmaxf(acc[nt][0], 0.f)));
            hs[(r0 + rA) * 68 + col + 1]   = __uint_as_float(f2tf32(fmaxf(acc[nt][1], 0.f)));
            hs[(r0 + 8 + rA) * 68 + col]     = __uint_as_float(f2tf32(fmaxf(acc[nt][2], 0.f)));
            hs[(r0 + 8 + rA) * 68 + col + 1] = __uint_as_float(f2tf32(fmaxf(acc[nt][3], 0.f)));
        }
    }
    __syncthreads();

    {
        float acc[4][4];
        #pragma unroll
        for (int nt = 0; nt < 4; nt++)
            #pragma unroll
            for (int q = 0; q < 4; q++) acc[nt][q] = 0.f;
        #pragma unroll
        for (int kt = 0; kt < 8; kt++) {
            int cA = kt * 8 + (lane & 3);
            unsigned a[4];
            a[0] = __float_as_uint(hs[(r0 + rA) * 68 + cA]);
            a[1] = __float_as_uint(hs[(r0 + 8 + rA) * 68 + cA]);
            a[2] = __float_as_uint(hs[(r0 + rA) * 68 + cA + 4]);
            a[3] = __float_as_uint(hs[(r0 + 8 + rA) * 68 + cA + 4]);
            #pragma unroll
            for (int nt = 0; nt < 4; nt++) {
                float2 b = ((const float2*)g_fWlin)[(kt * 8 + nh * 4 + nt) * 32 + lane];
                MMA_TF32(acc[nt], a, __float_as_uint(b.x), __float_as_uint(b.y));
            }
        }
        #pragma unroll
        for (int nt = 0; nt < 4; nt++) {
            int col = n0 + nt * 8 + cb;
            vs[(r0 + rA) * 68 + col]         = acc[nt][0];
            vs[(r0 + rA) * 68 + col + 1]     = acc[nt][1];
            vs[(r0 + 8 + rA) * 68 + col]     = acc[nt][2];
            vs[(r0 + 8 + rA) * 68 + col + 1] = acc[nt][3];
            if (ok0) *(float2*)(g_v + (size_t)rowg0 * C + col) = make_float2(acc[nt][0], acc[nt][1]);
            if (ok1) *(float2*)(g_v + (size_t)rowg1 * C + col) = make_float2(acc[nt][2], acc[nt][3]);
        }
    }
    {
        float aq[4][4], ak[4][4];
        #pragma unroll
        for (int nt = 0; nt < 4; nt++)
            #pragma unroll
            for (int q = 0; q < 4; q++) { aq[nt][q] = 0.f; ak[nt][q] = 0.f; }
        #pragma unroll
        for (int kt = 0; kt < 8; kt++) {
            int cA = kt * 8 + (lane & 3);
            unsigned a[4];
            a[0] = __float_as_uint(hs[(r0 + rA) * 68 + cA]);
            a[1] = __float_as_uint(hs[(r0 + 8 + rA) * 68 + cA]);
            a[2] = __float_as_uint(hs[(r0 + rA) * 68 + cA + 4]);
            a[3] = __float_as_uint(hs[(r0 + 8 + rA) * 68 + cA + 4]);
            #pragma unroll
            for (int nt = 0; nt < 4; nt++) {
                float2 bq = ((const float2*)g_fMq)[(kt * 8 + nh * 4 + nt) * 32 + lane];
                float2 bk = ((const float2*)g_fMk)[(kt * 8 + nh * 4 + nt) * 32 + lane];
                MMA_TF32(aq[nt], a, __float_as_uint(bq.x), __float_as_uint(bq.y));
                MMA_TF32(ak[nt], a, __float_as_uint(bk.x), __float_as_uint(bk.y));
            }
        }
        #pragma unroll
        for (int nt = 0; nt < 4; nt++) {
            int col = n0 + nt * 8 + cb;
            float ba0 = att_b1[col], ba1 = att_b1[col + 1];
            xs[(r0 + rA) * 68 + col]       = __uint_as_float(f2tf32(fmaxf(aq[nt][0] - ak[nt][0] + ba0, 0.f)));
            xs[(r0 + rA) * 68 + col + 1]   = __uint_as_float(f2tf32(fmaxf(aq[nt][1] - ak[nt][1] + ba1, 0.f)));
            xs[(r0 + 8 + rA) * 68 + col]     = __uint_as_float(f2tf32(fmaxf(aq[nt][2] - ak[nt][2] + ba0, 0.f)));
            xs[(r0 + 8 + rA) * 68 + col + 1] = __uint_as_float(f2tf32(fmaxf(aq[nt][3] - ak[nt][3] + ba1, 0.f)));
            if (ok0) {
                *(__half2*)(g_hQ1 + (size_t)rowg0 * C + col) = __floats2half2_rn(aq[nt][0], aq[nt][1]);
                *(__half2*)(g_hK1 + (size_t)rowg0 * C + col) = __floats2half2_rn(ak[nt][0], ak[nt][1]);
            }
            if (ok1) {
                *(__half2*)(g_hQ1 + (size_t)rowg1 * C + col) = __floats2half2_rn(aq[nt][2], aq[nt][3]);
                *(__half2*)(g_hK1 + (size_t)rowg1 * C + col) = __floats2half2_rn(ak[nt][2], ak[nt][3]);
            }
        }
    }
    __syncthreads();

    {
        float acc[4][4];
        #pragma unroll
        for (int nt = 0; nt < 4; nt++) {
            int col = n0 + nt * 8 + cb;
            float b0 = att_b2[col], b1 = att_b2[col + 1];
            acc[nt][0] = b0; acc[nt][1] = b1; acc[nt][2] = b0; acc[nt][3] = b1;
        }
        #pragma unroll
        for (int kt = 0; kt < 8; kt++) {
            int cA = kt * 8 + (lane & 3);
            unsigned a[4];
            a[0] = __float_as_uint(xs[(r0 + rA) * 68 + cA]);
            a[1] = __float_as_uint(xs[(r0 + 8 + rA) * 68 + cA]);
            a[2] = __float_as_uint(xs[(r0 + rA) * 68 + cA + 4]);
            a[3] = __float_as_uint(xs[(r0 + 8 + rA) * 68 + cA + 4]);
            #pragma unroll
            for (int nt = 0; nt < 4; nt++) {
                float2 b = ((const float2*)g_fW2a)[(kt * 8 + nh * 4 + nt) * 32 + lane];
                MMA_TF32(acc[nt], a, __float_as_uint(b.x), __float_as_uint(b.y));
            }
        }
        #pragma unroll
        for (int nt = 0; nt < 4; nt++) {
            int col = n0 + nt * 8 + cb;
            float d0 = g_delta0[col], d1 = g_delta0[col + 1];
            float e0 = __expf(fmaxf(acc[nt][0], 0.f));
            float e1 = __expf(fmaxf(acc[nt][1], 0.f));
            float e2 = __expf(fmaxf(acc[nt][2], 0.f));
            float e3 = __expf(fmaxf(acc[nt][3], 0.f));
            if (ok0) {
                float v0 = vs[(r0 + rA) * 68 + col];
                float v1 = vs[(r0 + rA) * 68 + col + 1];
                *(float2*)(g_den + (size_t)rowg0 * C + col) = make_float2(e0, e1);
                *(float2*)(g_num + (size_t)rowg0 * C + col) = make_float2(e0 * (v0 + d0), e1 * (v1 + d1));
            }
            if (ok1) {
                float v2 = vs[(r0 + 8 + rA) * 68 + col];
                float v3 = vs[(r0 + 8 + rA) * 68 + col + 1];
                *(float2*)(g_den + (size_t)rowg1 * C + col) = make_float2(e2, e3);
                *(float2*)(g_num + (size_t)rowg1 * C + col) = make_float2(e2 * (v2 + d0), e3 * (v3 + d1));
            }
        }
    }
}

// ---------------- K2: edge kernel — latency-pipelined half-pipelines ------------
// Per-half smem (offset h*35840 bytes):
//   [0, 9216)       hidA16  2 bufs x 32 rows x 72 halves
//   [9216, 18432)   hidP16  2 bufs
//   [18432, 27136)  exA     32 x 68 fp32 (single buffer)
//   [27136, 35840)  dlP
__global__ void __launch_bounds__(256, 2)
edge_kernel(const int* __restrict__ src, const int* __restrict__ dst,
            const float* __restrict__ att_b1, const float* __restrict__ pos_b1,
            const float* __restrict__ pos_w1,
            const float* __restrict__ att_b2, const float* __restrict__ pos_b2,
            int E)
{
    extern __shared__ char smE[];
    int tid  = threadIdx.x;
    int lane = tid & 31;
    int wid  = tid >> 5;
    bool isA = (wid < 4);
    int sub  = wid & 3;
    int h    = sub >> 1;
    int nhE  = sub & 1;
    int n0b  = nhE * 32;

    char* hb = smE + h * 35840;
    __half* hidA0 = (__half*)hb;              // buf stride 2304 halves (4608 B)
    __half* hidP0 = (__half*)(hb + 9216);
    float*  exA   = (float*)(hb + 18432);
    float*  dlP   = (float*)(hb + 27136);

    const float* b2 = isA ? att_b2 : pos_b2;
    float* res = isA ? exA : dlP;

    uint2 bB[4][4];
    {
        const uint2* hw2 = isA ? g_hW2a : g_hW2p;
        #pragma unroll
        for (int kt = 0; kt < 4; kt++)
            #pragma unroll
            for (int nt = 0; nt < 4; nt++)
                bB[kt][nt] = hw2[((kt * 8) + nhE * 4 + nt) * 32 + lane];
    }
    float bias0[4], bias1[4];
    #pragma unroll
    for (int nt = 0; nt < 4; nt++) {
        int col = n0b + nt * 8 + 2 * (lane & 3);
        bias0[nt] = b2[col];
        bias1[nt] = b2[col + 1];
    }

    int hwi  = (wid & 1) | ((wid >> 2) << 1);
    int htid = hwi * 32 + lane;
    int hgrp = htid >> 4;
    int js   = (htid & 15) << 2;

    float4 ba1 = *(const float4*)(att_b1 + js);
    __half2 ba1h0 = __floats2half2_rn(ba1.x, ba1.y);
    __half2 ba1h1 = __floats2half2_rn(ba1.z, ba1.w);
    __half2 hzero = __floats2half2_rn(0.f, 0.f);
    float4 bp1 = *(const float4*)(pos_b1 + js);
    float4 pwx, pwy, pwz;
    {
        float3 w0 = *(const float3*)(pos_w1 + (js + 0) * 3);
        float3 w1 = *(const float3*)(pos_w1 + (js + 1) * 3);
        float3 w2 = *(const float3*)(pos_w1 + (js + 2) * 3);
        float3 w3 = *(const float3*)(pos_w1 + (js + 3) * 3);
        pwx = make_float4(w0.x, w1.x, w2.x, w3.x);
        pwy = make_float4(w0.y, w1.y, w2.y, w3.y);
        pwz = make_float4(w0.z, w1.z, w2.z, w3.z);
    }

    uint32_t hidBase;
    asm("{ .reg .u64 t; cvta.to.shared.u64 t, %1; cvt.u32.u64 %0, t; }"
        : "=r"(hidBase) : "l"(isA ? hidA0 : hidP0));
    uint32_t aAddr0 = hidBase + (uint32_t)((((lane & 15)) * 72 + ((lane >> 4) << 3)) * 2);
    uint32_t aAddr1 = hidBase + (uint32_t)(((16 + (lane & 15)) * 72 + ((lane >> 4) << 3)) * 2);

    int nvt    = (E + 31) >> 5;
    int H      = blockIdx.x * 2 + h;
    int stride = gridDim.x * 2;
    int barId  = h + 1;
    int L      = (H < nvt) ? ((nvt - H + stride - 1) / stride) : 0;
    if (L == 0) return;

    int sNxt[4], dNxt[4], sCur[4], dCur[4];

    // ---- prologue: idx(t0), compute hid(t0) into buf0, idx(t1) ----
    #pragma unroll
    for (int k = 0; k < 4; k++) {
        int ge = (H << 5) + hgrp + 8 * k;
        sNxt[k] = (ge < E) ? src[ge] : 0;
        dNxt[k] = (ge < E) ? dst[ge] : -1;
    }
    #pragma unroll
    for (int k = 0; k < 4; k++) {
        int e = hgrp + 8 * k;
        int s = sNxt[k], d = dNxt[k];
        int dc = d < 0 ? 0 : d;
        uint2 qu = *(const uint2*)(g_hQ1 + (size_t)dc * C + js);
        uint2 ku = *(const uint2*)(g_hK1 + (size_t)s  * C + js);
        float4 p4d = g_pos4[dc];
        float4 p4s = g_pos4[s];
        float dpx = p4d.x - p4s.x, dpy = p4d.y - p4s.y, dpz = p4d.z - p4s.z;
        uint2 ua, up;
        if (d >= 0) {
            __half2 q0 = *(__half2*)&qu.x, q1 = *(__half2*)&qu.y;
            __half2 k0 = *(__half2*)&ku.x, k1 = *(__half2*)&ku.y;
            __half2 a0 = __hmax2(__hadd2(__hsub2(q0, k0), ba1h0), hzero);
            __half2 a1 = __hmax2(__hadd2(__hsub2(q1, k1), ba1h1), hzero);
            ua.x = *(unsigned*)&a0;
            ua.y = *(unsigned*)&a1;
            float r0p = fmaf(dpx, pwx.x, fmaf(dpy, pwy.x, fmaf(dpz, pwz.x, bp1.x)));
            float r1p = fmaf(dpx, pwx.y, fmaf(dpy, pwy.y, fmaf(dpz, pwz.y, bp1.y)));
            float r2p = fmaf(dpx, pwx.z, fmaf(dpy, pwy.z, fmaf(dpz, pwz.z, bp1.z)));
            float r3p = fmaf(dpx, pwx.w, fmaf(dpy, pwy.w, fmaf(dpz, pwz.w, bp1.w)));
            up.x = pack_h2(fmaxf(r0p, 0.f), fmaxf(r1p, 0.f));
            up.y = pack_h2(fmaxf(r2p, 0.f), fmaxf(r3p, 0.f));
        } else {
            ua = make_uint2(0u, 0u);
            up = ua;
        }
        *(uint2*)(hidA0 + e * 72 + js) = ua;
        *(uint2*)(hidP0 + e * 72 + js) = up;
    }
    #pragma unroll
    for (int k = 0; k < 4; k++) { sCur[k] = sNxt[k]; dCur[k] = dNxt[k]; }
    if (L > 1) {
        int t1 = H + stride;
        #pragma unroll
        for (int k = 0; k < 4; k++) {
            int ge = (t1 << 5) + hgrp + 8 * k;
            sNxt[k] = (ge < E) ? src[ge] : 0;
            dNxt[k] = (ge < E) ? dst[ge] : -1;
        }
    } else {
        #pragma unroll
        for (int k = 0; k < 4; k++) { sNxt[k] = 0; dNxt[k] = -1; }
    }
    HBAR(barId);

    // ---- main loop ----
    int b = 0;
    for (int i = 0; i < L; i++, b ^= 1) {
        bool hasNext = (i + 1 < L);

        // 1. issue Q/K loads for tile t+1 (consumed in step 5 — latency hidden)
        uint2 qu[4], ku[4];
        if (hasNext) {
            #pragma unroll
            for (int k = 0; k < 4; k++) {
                int dc = dNxt[k] < 0 ? 0 : dNxt[k];
                qu[k] = *(const uint2*)(g_hQ1 + (size_t)dc * C + js);
                ku[k] = *(const uint2*)(g_hK1 + (size_t)sNxt[k] * C + js);
            }
        }

        // 2. MMA(t) from hid buf b + epilogue -> res
        {
            float acc[2][4][4];
            #pragma unroll
            for (int s2 = 0; s2 < 2; s2++)
                #pragma unroll
                for (int nt = 0; nt < 4; nt++) {
                    acc[s2][nt][0] = bias0[nt];
                    acc[s2][nt][1] = bias1[nt];
                    acc[s2][nt][2] = bias0[nt];
                    acc[s2][nt][3] = bias1[nt];
                }
            uint32_t bo = b ? 4608u : 0u;
            #pragma unroll
            for (int kt = 0; kt < 4; kt++) {
                unsigned a0[4], a1[4];
                ldsm_x4(a0[0], a0[1], a0[2], a0[3], aAddr0 + bo + kt * 32);
                ldsm_x4(a1[0], a1[1], a1[2], a1[3], aAddr1 + bo + kt * 32);
                #pragma unroll
                for (int nt = 0; nt < 4; nt++) {
                    MMA_F16(acc[0][nt], a0, bB[kt][nt].x, bB[kt][nt].y);
                    MMA_F16(acc[1][nt], a1, bB[kt][nt].x, bB[kt][nt].y);
                }
            }
            int rA = lane >> 2;
            int cbv = 2 * (lane & 3);
            #pragma unroll
            for (int s2 = 0; s2 < 2; s2++) {
                int rb = s2 * 16 + rA;
                #pragma unroll
                for (int nt = 0; nt < 4; nt++) {
                    int col = n0b + nt * 8 + cbv;
                    float v0, v1, v2, v3;
                    if (isA) {
                        v0 = __expf(fmaxf(acc[s2][nt][0], 0.f));
                        v1 = __expf(fmaxf(acc[s2][nt][1], 0.f));
                        v2 = __expf(fmaxf(acc[s2][nt][2], 0.f));
                        v3 = __expf(fmaxf(acc[s2][nt][3], 0.f));
                    } else {
                        v0 = fmaxf(acc[s2][nt][0], 0.f);
                        v1 = fmaxf(acc[s2][nt][1], 0.f);
                        v2 = fmaxf(acc[s2][nt][2], 0.f);
                        v3 = fmaxf(acc[s2][nt][3], 0.f);
                    }
                    *(float2*)(res + rb * 68 + col)       = make_float2(v0, v1);
                    *(float2*)(res + (rb + 8) * 68 + col) = make_float2(v2, v3);
                }
            }
        }
        HBAR(barId);

        // 4. scatter(t)
        #pragma unroll
        for (int k = 0; k < 4; k++) {
            int d = dCur[k];
            if (d >= 0) {
                int e = hgrp + 8 * k;
                float4 ex = *(const float4*)(exA + e * 68 + js);
                float4 dl = *(const float4*)(dlP + e * 68 + js);
                float4 vv = *(const float4*)(g_v + (size_t)sCur[k] * C + js);
                float4 nv;
                nv.x = ex.x * (vv.x + dl.x);
                nv.y = ex.y * (vv.y + dl.y);
                nv.z = ex.z * (vv.z + dl.z);
                nv.w = ex.w * (vv.w + dl.w);
                RED_V4(g_num + (size_t)d * C + js, nv);
                RED_V4(g_den + (size_t)d * C + js, ex);
            }
        }

        // 5. compute + store hid(t+1) into buf b^1 (consumes step-1 loads)
        if (hasNext) {
            int bufN = (b ^ 1) ? 2304 : 0;
            #pragma unroll
            for (int k = 0; k < 4; k++) {
                int e = hgrp + 8 * k;
                int s = sNxt[k], d = dNxt[k];
                int dc = d < 0 ? 0 : d;
                float4 p4d = g_pos4[dc];
                float4 p4s = g_pos4[s];
                float dpx = p4d.x - p4s.x, dpy = p4d.y - p4s.y, dpz = p4d.z - p4s.z;
                uint2 ua, up;
                if (d >= 0) {
                    __half2 q0 = *(__half2*)&qu[k].x, q1 = *(__half2*)&qu[k].y;
                    __half2 k0 = *(__half2*)&ku[k].x, k1 = *(__half2*)&ku[k].y;
                    __half2 a0 = __hmax2(__hadd2(__hsub2(q0, k0), ba1h0), hzero);
                    __half2 a1 = __hmax2(__hadd2(__hsub2(q1, k1), ba1h1), hzero);
                    ua.x = *(unsigned*)&a0;
                    ua.y = *(unsigned*)&a1;
                    float r0p = fmaf(dpx, pwx.x, fmaf(dpy, pwy.x, fmaf(dpz, pwz.x, bp1.x)));
                    float r1p = fmaf(dpx, pwx.y, fmaf(dpy, pwy.y, fmaf(dpz, pwz.y, bp1.y)));
                    float r2p = fmaf(dpx, pwx.z, fmaf(dpy, pwy.z, fmaf(dpz, pwz.z, bp1.z)));
                    float r3p = fmaf(dpx, pwx.w, fmaf(dpy, pwy.w, fmaf(dpz, pwz.w, bp1.w)));
                    up.x = pack_h2(fmaxf(r0p, 0.f), fmaxf(r1p, 0.f));
                    up.y = pack_h2(fmaxf(r2p, 0.f), fmaxf(r3p, 0.f));
                } else {
                    ua = make_uint2(0u, 0u);
                    up = ua;
                }
                *(uint2*)(hidA0 + bufN + e * 72 + js) = ua;
                *(uint2*)(hidP0 + bufN + e * 72 + js) = up;
            }
        }

        // 6. rotate indices + prefetch idx(t+2)
        #pragma unroll
        for (int k = 0; k < 4; k++) { sCur[k] = sNxt[k]; dCur[k] = dNxt[k]; }
        if (i + 2 < L) {
            int t2 = H + (i + 2) * stride;
            #pragma unroll
            for (int k = 0; k < 4; k++) {
                int ge = (t2 << 5) + hgrp + 8 * k;
                sNxt[k] = (ge < E) ? src[ge] : 0;
                dNxt[k] = (ge < E) ? dst[ge] : -1;
            }
        } else {
            #pragma unroll
            for (int k = 0; k < 4; k++) { sNxt[k] = 0; dNxt[k] = -1; }
        }
        HBAR(barId);
    }
}

// ---------------- K3: out kernel — tf32 MMA over 64-node tiles ------------------
__global__ void __launch_bounds__(256)
out_kernel(const float* __restrict__ b_out, float* __restrict__ out, int n)
{
    __shared__ float rs[64 * 68];
    int tid  = threadIdx.x;
    int lane = tid & 31;
    int wid  = tid >> 5;
    int base = blockIdx.x * 64;

    for (int t = tid; t < 1024; t += 256) {
        int row = t >> 4;
        int col = (t & 15) * 4;
        int node = base + row;
        float4 r = make_float4(0.f, 0.f, 0.f, 0.f);
        if (node < n) {
            float4 nu = *(const float4*)(g_num + (size_t)node * C + col);
            float4 de = *(const float4*)(g_den + (size_t)node * C + col);
            r.x = __uint_as_float(f2tf32(nu.x / (de.x + 1e-16f)));
            r.y = __uint_as_float(f2tf32(nu.y / (de.y + 1e-16f)));
            r.z = __uint_as_float(f2tf32(nu.z / (de.z + 1e-16f)));
            r.w = __uint_as_float(f2tf32(nu.w / (de.w + 1e-16f)));
        }
        *(float4*)(rs + row * 68 + col) = r;
    }
    __syncthreads();

    int r0 = (wid & 3) * 16;
    int nh = wid >> 2;
    int n0 = nh * 32;
    int rA = lane >> 2;
    int cb = 2 * (lane & 3);
    int rowg0 = base + r0 + rA;
    int rowg1 = rowg0 + 8;

    float acc[4][4];
    #pragma unroll
    for (int nt = 0; nt < 4; nt++) {
        int col = n0 + nt * 8 + cb;
        float b0 = b_out[col], b1 = b_out[col + 1];
        acc[nt][0] = b0; acc[nt][1] = b1; acc[nt][2] = b0; acc[nt][3] = b1;
    }
    #pragma unroll
    for (int kt = 0; kt < 8; kt++) {
        int cA = kt * 8 + (lane & 3);
        unsigned a[4];
        a[0] = __float_as_uint(rs[(r0 + rA) * 68 + cA]);
        a[1] = __float_as_uint(rs[(r0 + 8 + rA) * 68 + cA]);
        a[2] = __float_as_uint(rs[(r0 + rA) * 68 + cA + 4]);
        a[3] = __float_as_uint(rs[(r0 + 8 + rA) * 68 + cA + 4]);
        #pragma unroll
        for (int nt = 0; nt < 4; nt++) {
            float2 b = ((const float2*)g_fWout)[(kt * 8 + nh * 4 + nt) * 32 + lane];
            MMA_TF32(acc[nt], a, __float_as_uint(b.x), __float_as_uint(b.y));
        }
    }
    #pragma unroll
    for (int nt = 0; nt < 4; nt++) {
        int col = n0 + nt * 8 + cb;
        if (rowg0 < n)
            *(float2*)(out + (size_t)rowg0 * C + col) =
                make_float2(fmaxf(acc[nt][0], 0.f), fmaxf(acc[nt][1], 0.f));
        if (rowg1 < n)
            *(float2*)(out + (size_t)rowg1 * C + col) =
                make_float2(fmaxf(acc[nt][2], 0.f), fmaxf(acc[nt][3], 0.f));
    }
}

// ---------------- launch --------------------------------------------------------
extern "C" void kernel_launch(void* const* d_in, const int* in_sizes, int n_in,
                              void* d_out, int out_size)
{
    const float* x      = (const float*)d_in[0];
    const float* pos    = (const float*)d_in[1];
    const int*   ei     = (const int*)  d_in[2];
    const float* W_in   = (const float*)d_in[3];
    const float* b_in   = (const float*)d_in[4];
    const float* W_out  = (const float*)d_in[5];
    const float* b_out  = (const float*)d_in[6];
    const float* W_lin  = (const float*)d_in[7];
    const float* W_src  = (const float*)d_in[8];
    const float* W_dst  = (const float*)d_in[9];
    const float* pos_w1 = (const float*)d_in[10];
    const float* pos_b1 = (const float*)d_in[11];
    const float* pos_w2 = (const float*)d_in[12];
    const float* pos_b2 = (const float*)d_in[13];
    const float* att_w1 = (const float*)d_in[14];
    const float* att_b1 = (const float*)d_in[15];
    const float* att_w2 = (const float*)d_in[16];
    const float* att_b2 = (const float*)d_in[17];

    int n = in_sizes[0] / C;
    int E = in_sizes[2] / 2;
    const int* srcArr = ei;
    const int* dstArr = ei + E;

    size_t smemNode = (size_t)(3 * 64 * 68) * sizeof(float);   // 52224
    size_t smemEdge = 71680;                                   // 2 x 35840
    cudaFuncSetAttribute(node_kernel, cudaFuncAttributeMaxDynamicSharedMemorySize, (int)smemNode);
    cudaFuncSetAttribute(edge_kernel, cudaFuncAttributeMaxDynamicSharedMemorySize, (int)smemEdge);

    int tilesN = (n + 63) / 64;

    prep_kernel<<<1, 256>>>(att_w1, W_dst, W_src, W_in, W_lin, att_w2, pos_w2, W_out,
                            pos_b1, pos_b2);
    node_kernel<<<tilesN, 256, smemNode>>>(x, pos, b_in, att_b1, att_b2, n);
    spacer_kernel<<<1, 32>>>();   // keeps edge_kernel at launch #4 (ncu capture slot)
    edge_kernel<<<296, 256, smemEdge>>>(srcArr, dstArr, att_b1, pos_b1, pos_w1,
                                        att_b2, pos_b2, E);
    out_kernel<<<tilesN, 256>>>(b_out, (float*)d_out, n);
}

// round 15
// speedup vs baseline: 1.0729x; 1.0729x over previous
#include <cuda_runtime.h>
#include <cuda_fp16.h>
#include <cstdint>

#define C 64
#define MAXN 50000
#define MAXE 800000

// ---------------- device scratch (static: no allocation allowed) ----------------
__device__ float  g_v[MAXN * C];
__device__ __half g_hQ1[MAXN * C];
__device__ __half g_hK1[MAXN * C];
__device__ float4 g_pos4[MAXN];
__device__ float  g_num[MAXN * C];
__device__ float  g_den[MAXN * C];
__device__ float g_Mq_t[C * C];
__device__ float g_Mk_t[C * C];
__device__ float g_Win_t[C * C];
__device__ float g_Wlin_t[C * C];
__device__ float g_w2a_t[C * C];
__device__ float g_w2p_t[C * C];
__device__ float g_Wout_t[C * C];
__device__ float g_delta0[C];
// fp16 B fragments (m16n8k16): [(kt*8+nt)*32+lane] -> uint2 {b0,b1}
__device__ uint2 g_hWin[1024];
__device__ uint2 g_hWlin[1024];
__device__ uint2 g_hMq[1024];
__device__ uint2 g_hMk[1024];
__device__ uint2 g_hW2a[1024];
__device__ uint2 g_hW2p[1024];
__device__ uint2 g_hWout[1024];

__device__ __forceinline__ unsigned pack_h2(float a, float b) {
    __half2 h = __floats2half2_rn(a, b);
    return *reinterpret_cast<unsigned*>(&h);
}

#define MMA_F16(d, a, b0, b1)                                                \
    asm volatile("mma.sync.aligned.m16n8k16.row.col.f32.f16.f16.f32 "        \
                 "{%0,%1,%2,%3}, {%4,%5,%6,%7}, {%8,%9}, {%0,%1,%2,%3};"     \
                 : "+f"(d[0]), "+f"(d[1]), "+f"(d[2]), "+f"(d[3])            \
                 : "r"(a[0]), "r"(a[1]), "r"(a[2]), "r"(a[3]),               \
                   "r"(b0), "r"(b1))

#define RED_V4(ptr, v)                                                       \
    asm volatile("red.global.add.v4.f32 [%0], {%1,%2,%3,%4};"                \
                 :: "l"(ptr), "f"((v).x), "f"((v).y), "f"((v).z), "f"((v).w) \
                 : "memory")

#define HBAR(id)                                                             \
    asm volatile("bar.sync %0, 128;" :: "r"(id) : "memory")

__device__ __forceinline__ void ldsm_x4(unsigned& r0, unsigned& r1,
                                        unsigned& r2, unsigned& r3, unsigned addr) {
    asm volatile("ldmatrix.sync.aligned.m8n8.x4.shared.b16 {%0,%1,%2,%3}, [%4];"
                 : "=r"(r0), "=r"(r1), "=r"(r2), "=r"(r3) : "r"(addr));
}

__device__ __forceinline__ uint32_t smem_u32(const void* p) {
    uint32_t r;
    asm("{ .reg .u64 t; cvta.to.shared.u64 t, %1; cvt.u32.u64 %0, t; }"
        : "=r"(r) : "l"(p));
    return r;
}

// ---------------- K0: weight prep ------------------------------------------------
__global__ void prep_kernel(const float* __restrict__ att_w1,
                            const float* __restrict__ W_dst,
                            const float* __restrict__ W_src,
                            const float* __restrict__ W_in,
                            const float* __restrict__ W_lin,
                            const float* __restrict__ att_w2,
                            const float* __restrict__ pos_w2,
                            const float* __restrict__ W_out,
                            const float* __restrict__ pos_b1,
                            const float* __restrict__ pos_b2)
{
    __shared__ float s_a[C * C];
    __shared__ float s_d[C * C];
    __shared__ float s_s[C * C];
    int tid = threadIdx.x;
    for (int t = tid; t < C * C; t += blockDim.x) {
        s_a[t] = att_w1[t];
        s_d[t] = W_dst[t];
        s_s[t] = W_src[t];
    }
    __syncthreads();
    for (int idx = tid; idx < C * C; idx += blockDim.x) {
        int t = idx >> 6, j = idx & 63;
        float aq = 0.f, ak = 0.f;
        #pragma unroll 8
        for (int u = 0; u < C; u++) {
            float a = s_a[t * C + u];
            aq = fmaf(a, s_d[u * C + j], aq);
            ak = fmaf(a, s_s[u * C + j], ak);
        }
        g_Mq_t[j * C + t] = aq;
        g_Mk_t[j * C + t] = ak;
    }
    for (int idx = tid; idx < C * C; idx += blockDim.x) {
        int cc = idx >> 6, j = idx & 63;
        g_Win_t[j * C + cc]  = W_in[idx];
        g_Wlin_t[j * C + cc] = W_lin[idx];
        g_w2a_t[j * C + cc]  = att_w2[idx];
        g_w2p_t[j * C + cc]  = pos_w2[idx];
        g_Wout_t[j * C + cc] = W_out[idx];
    }
    if (tid < C) {
        float acc = pos_b2[tid];
        #pragma unroll 8
        for (int j = 0; j < C; j++)
            acc = fmaf(fmaxf(pos_b1[j], 0.f), pos_w2[tid * C + j], acc);
        g_delta0[tid] = fmaxf(acc, 0.f);
    }
    __syncthreads();
    // fp16 B fragments (m16n8k16) for all seven matrices
    for (int t = tid; t < 1024; t += blockDim.x) {
        int kt   = t >> 8;
        int nt   = (t >> 5) & 7;
        int lane = t & 31;
        int tig = lane & 3, gid = lane >> 2;
        int n  = nt * 8 + gid;
        int k0 = kt * 16 + tig * 2;
        #define BUILD(dst, srcm)                                             \
            { uint2 u;                                                        \
              u.x = pack_h2(srcm[k0 * 64 + n],       srcm[(k0 + 1) * 64 + n]);\
              u.y = pack_h2(srcm[(k0 + 8) * 64 + n], srcm[(k0 + 9) * 64 + n]);\
              dst[t] = u; }
        BUILD(g_hWin,  g_Win_t)
        BUILD(g_hWlin, g_Wlin_t)
        BUILD(g_hMq,   g_Mq_t)
        BUILD(g_hMk,   g_Mk_t)
        BUILD(g_hW2a,  g_w2a_t)
        BUILD(g_hW2p,  g_w2p_t)
        BUILD(g_hWout, g_Wout_t)
        #undef BUILD
    }
}

// ---------------- dummy (instrumentation spacer so ncu window hits edge_kernel) --
__global__ void spacer_kernel() {}

// ---------------- K1: node kernel — fp16 MMA, 4 fused GEMM passes ---------------
// smem: xs half[64*72] @0 (9216B), hs half[64*72] @9216, vs float[64*68] @18432
__global__ void __launch_bounds__(256)
node_kernel(const float* __restrict__ x,
            const float* __restrict__ pos,
            const float* __restrict__ b_in,
            const float* __restrict__ att_b1,
            const float* __restrict__ att_b2,
            int n)
{
    extern __shared__ char smN[];
    __half* xs = (__half*)smN;
    __half* hs = (__half*)(smN + 9216);
    float*  vs = (float*)(smN + 18432);
    int tid  = threadIdx.x;
    int lane = tid & 31;
    int wid  = tid >> 5;
    int base = blockIdx.x * 64;

    for (int t = tid; t < 1024; t += 256) {
        int row = t >> 4;
        int col = (t & 15) * 4;
        int node = base + row;
        float4 v4 = make_float4(0.f, 0.f, 0.f, 0.f);
        if (node < n) v4 = *(const float4*)(x + (size_t)node * C + col);
        uint2 u;
        u.x = pack_h2(v4.x, v4.y);
        u.y = pack_h2(v4.z, v4.w);
        *(uint2*)(xs + row * 72 + col) = u;
    }
    if (tid < 64) {
        int node = base + tid;
        if (node < n) {
            g_pos4[node] = make_float4(pos[(size_t)node * 3 + 0],
                                       pos[(size_t)node * 3 + 1],
                                       pos[(size_t)node * 3 + 2], 0.f);
        }
    }
    __syncthreads();

    int r0 = (wid & 3) * 16;
    int nh = wid >> 2;
    int n0 = nh * 32;
    int rA = lane >> 2;
    int cb = 2 * (lane & 3);
    int rowg0 = base + r0 + rA;
    int rowg1 = rowg0 + 8;
    bool ok0 = rowg0 < n, ok1 = rowg1 < n;

    uint32_t aX = smem_u32(xs) + (uint32_t)(((r0 + (lane & 15)) * 72 + ((lane >> 4) << 3)) * 2);
    uint32_t aH = smem_u32(hs) + (uint32_t)(((r0 + (lane & 15)) * 72 + ((lane >> 4) << 3)) * 2);

    // ---- GEMM1: h = relu(x @ Win^T + b_in) -> hs (fp16) ----
    {
        float acc[4][4];
        #pragma unroll
        for (int nt = 0; nt < 4; nt++) {
            int col = n0 + nt * 8 + cb;
            float b0 = b_in[col], b1 = b_in[col + 1];
            acc[nt][0] = b0; acc[nt][1] = b1; acc[nt][2] = b0; acc[nt][3] = b1;
        }
        #pragma unroll
        for (int kt = 0; kt < 4; kt++) {
            unsigned a[4];
            ldsm_x4(a[0], a[1], a[2], a[3], aX + kt * 32);
            #pragma unroll
            for (int nt = 0; nt < 4; nt++) {
                uint2 b = g_hWin[(kt * 8 + nh * 4 + nt) * 32 + lane];
                MMA_F16(acc[nt], a, b.x, b.y);
            }
        }
        #pragma unroll
        for (int nt = 0; nt < 4; nt++) {
            int col = n0 + nt * 8 + cb;
            *(unsigned*)(hs + (r0 + rA) * 72 + col) =
                pack_h2(fmaxf(acc[nt][0], 0.f), fmaxf(acc[nt][1], 0.f));
            *(unsigned*)(hs + (r0 + 8 + rA) * 72 + col) =
                pack_h2(fmaxf(acc[nt][2], 0.f), fmaxf(acc[nt][3], 0.f));
        }
    }
    __syncthreads();

    // ---- GEMM2 fused: v = h@Wlin^T, q = h@Mq^T, k = h@Mk^T ----
    {
        float av[4][4], aq[4][4], ak[4][4];
        #pragma unroll
        for (int nt = 0; nt < 4; nt++)
            #pragma unroll
            for (int q = 0; q < 4; q++) { av[nt][q] = 0.f; aq[nt][q] = 0.f; ak[nt][q] = 0.f; }
        #pragma unroll
        for (int kt = 0; kt < 4; kt++) {
            unsigned a[4];
            ldsm_x4(a[0], a[1], a[2], a[3], aH + kt * 32);
            #pragma unroll
            for (int nt = 0; nt < 4; nt++) {
                int fi = (kt * 8 + nh * 4 + nt) * 32 + lane;
                uint2 bv = g_hWlin[fi];
                uint2 bq = g_hMq[fi];
                uint2 bk = g_hMk[fi];
                MMA_F16(av[nt], a, bv.x, bv.y);
                MMA_F16(aq[nt], a, bq.x, bq.y);
                MMA_F16(ak[nt], a, bk.x, bk.y);
            }
        }
        #pragma unroll
        for (int nt = 0; nt < 4; nt++) {
            int col = n0 + nt * 8 + cb;
            vs[(r0 + rA) * 68 + col]         = av[nt][0];
            vs[(r0 + rA) * 68 + col + 1]     = av[nt][1];
            vs[(r0 + 8 + rA) * 68 + col]     = av[nt][2];
            vs[(r0 + 8 + rA) * 68 + col + 1] = av[nt][3];
            if (ok0) *(float2*)(g_v + (size_t)rowg0 * C + col) = make_float2(av[nt][0], av[nt][1]);
            if (ok1) *(float2*)(g_v + (size_t)rowg1 * C + col) = make_float2(av[nt][2], av[nt][3]);
            float ba0 = att_b1[col], ba1 = att_b1[col + 1];
            *(unsigned*)(xs + (r0 + rA) * 72 + col) =
                pack_h2(fmaxf(aq[nt][0] - ak[nt][0] + ba0, 0.f),
                        fmaxf(aq[nt][1] - ak[nt][1] + ba1, 0.f));
            *(unsigned*)(xs + (r0 + 8 + rA) * 72 + col) =
                pack_h2(fmaxf(aq[nt][2] - ak[nt][2] + ba0, 0.f),
                        fmaxf(aq[nt][3] - ak[nt][3] + ba1, 0.f));
            if (ok0) {
                *(__half2*)(g_hQ1 + (size_t)rowg0 * C + col) = __floats2half2_rn(aq[nt][0], aq[nt][1]);
                *(__half2*)(g_hK1 + (size_t)rowg0 * C + col) = __floats2half2_rn(ak[nt][0], ak[nt][1]);
            }
            if (ok1) {
                *(__half2*)(g_hQ1 + (size_t)rowg1 * C + col) = __floats2half2_rn(aq[nt][2], aq[nt][3]);
                *(__half2*)(g_hK1 + (size_t)rowg1 * C + col) = __floats2half2_rn(ak[nt][2], ak[nt][3]);
            }
        }
    }
    __syncthreads();

    // ---- GEMM3: s = a @ W2a^T + b2; e = exp(relu(s)); init num/den ----
    {
        float acc[4][4];
        #pragma unroll
        for (int nt = 0; nt < 4; nt++) {
            int col = n0 + nt * 8 + cb;
            float b0 = att_b2[col], b1 = att_b2[col + 1];
            acc[nt][0] = b0; acc[nt][1] = b1; acc[nt][2] = b0; acc[nt][3] = b1;
        }
        #pragma unroll
        for (int kt = 0; kt < 4; kt++) {
            unsigned a[4];
            ldsm_x4(a[0], a[1], a[2], a[3], aX + kt * 32);
            #pragma unroll
            for (int nt = 0; nt < 4; nt++) {
                uint2 b = g_hW2a[(kt * 8 + nh * 4 + nt) * 32 + lane];
                MMA_F16(acc[nt], a, b.x, b.y);
            }
        }
        #pragma unroll
        for (int nt = 0; nt < 4; nt++) {
            int col = n0 + nt * 8 + cb;
            float d0 = g_delta0[col], d1 = g_delta0[col + 1];
            float e0 = __expf(fmaxf(acc[nt][0], 0.f));
            float e1 = __expf(fmaxf(acc[nt][1], 0.f));
            float e2 = __expf(fmaxf(acc[nt][2], 0.f));
            float e3 = __expf(fmaxf(acc[nt][3], 0.f));
            if (ok0) {
                float v0 = vs[(r0 + rA) * 68 + col];
                float v1 = vs[(r0 + rA) * 68 + col + 1];
                *(float2*)(g_den + (size_t)rowg0 * C + col) = make_float2(e0, e1);
                *(float2*)(g_num + (size_t)rowg0 * C + col) = make_float2(e0 * (v0 + d0), e1 * (v1 + d1));
            }
            if (ok1) {
                float v2 = vs[(r0 + 8 + rA) * 68 + col];
                float v3 = vs[(r0 + 8 + rA) * 68 + col + 1];
                *(float2*)(g_den + (size_t)rowg1 * C + col) = make_float2(e2, e3);
                *(float2*)(g_num + (size_t)rowg1 * C + col) = make_float2(e2 * (v2 + d0), e3 * (v3 + d1));
            }
        }
    }
}

// ---------------- K2: edge kernel — R13 champion (half-pipelines) ---------------
// Per-half smem (offset h*27136 bytes):
//   [0, 4608)      hidA16  32 rows x 72 halves
//   [4608, 9216)   hidP16
//   [9216, 17920)  exA     32 x 68 fp32
//   [17920, 26624) dlP
//   [26624, 26880) seB [2][32]
//   [26880, 27136) deB [2][32]
__global__ void __launch_bounds__(256, 3)
edge_kernel(const int* __restrict__ src, const int* __restrict__ dst,
            const float* __restrict__ att_b1, const float* __restrict__ pos_b1,
            const float* __restrict__ pos_w1,
            const float* __restrict__ att_b2, const float* __restrict__ pos_b2,
            int E)
{
    extern __shared__ char smE[];
    int tid  = threadIdx.x;
    int lane = tid & 31;
    int wid  = tid >> 5;
    bool isA = (wid < 4);
    int sub  = wid & 3;
    int h    = sub >> 1;
    int nhE  = sub & 1;
    int n0b  = nhE * 32;

    char* hb = smE + h * 27136;
    __half* hidA16 = (__half*)hb;
    __half* hidP16 = (__half*)(hb + 4608);
    float*  exA    = (float*)(hb + 9216);
    float*  dlP    = (float*)(hb + 17920);
    int*    seB    = (int*)(hb + 26624);
    int*    deB    = (int*)(hb + 26880);

    const float* b2 = isA ? att_b2 : pos_b2;
    __half* hid = isA ? hidA16 : hidP16;
    float*  res = isA ? exA    : dlP;

    uint2 bB[4][4];
    {
        const uint2* hw2 = isA ? g_hW2a : g_hW2p;
        #pragma unroll
        for (int kt = 0; kt < 4; kt++)
            #pragma unroll
            for (int nt = 0; nt < 4; nt++)
                bB[kt][nt] = hw2[((kt * 8) + nhE * 4 + nt) * 32 + lane];
    }
    float bias0[4], bias1[4];
    #pragma unroll
    for (int nt = 0; nt < 4; nt++) {
        int col = n0b + nt * 8 + 2 * (lane & 3);
        bias0[nt] = b2[col];
        bias1[nt] = b2[col + 1];
    }

    int hwi  = (wid & 1) | ((wid >> 2) << 1);
    int htid = hwi * 32 + lane;
    int hgrp = htid >> 4;
    int js   = (htid & 15) << 2;

    float4 ba1 = *(const float4*)(att_b1 + js);
    __half2 ba1h0 = __floats2half2_rn(ba1.x, ba1.y);
    __half2 ba1h1 = __floats2half2_rn(ba1.z, ba1.w);
    __half2 hzero = __floats2half2_rn(0.f, 0.f);
    float4 bp1 = *(const float4*)(pos_b1 + js);
    float4 pwx, pwy, pwz;
    {
        float3 w0 = *(const float3*)(pos_w1 + (js + 0) * 3);
        float3 w1 = *(const float3*)(pos_w1 + (js + 1) * 3);
        float3 w2 = *(const float3*)(pos_w1 + (js + 2) * 3);
        float3 w3 = *(const float3*)(pos_w1 + (js + 3) * 3);
        pwx = make_float4(w0.x, w1.x, w2.x, w3.x);
        pwy = make_float4(w0.y, w1.y, w2.y, w3.y);
        pwz = make_float4(w0.z, w1.z, w2.z, w3.z);
    }

    uint32_t hidBase = smem_u32(hid);
    uint32_t aAddr0 = hidBase + (uint32_t)((((lane & 15)) * 72 + ((lane >> 4) << 3)) * 2);
    uint32_t aAddr1 = hidBase + (uint32_t)(((16 + (lane & 15)) * 72 + ((lane >> 4) << 3)) * 2);

    int sPrev[4], dPrev[4];
    #pragma unroll
    for (int k = 0; k < 4; k++) dPrev[k] = -1;

    int nvt    = (E + 31) >> 5;
    int H      = blockIdx.x * 2 + h;
    int stride = gridDim.x * 2;
    int barId  = h + 1;

    if (H < nvt) {
        if (htid < 32) {
            int e = (H << 5) + htid;
            seB[htid] = (e < E) ? src[e] : 0;
        } else if (htid < 64) {
            int e = (H << 5) + htid - 32;
            deB[htid - 32] = (e < E) ? dst[e] : -1;
        }
    }
    __syncthreads();

    int it = 0;
    for (int vt = H; vt < nvt; vt += stride, it ^= 1) {
        // ===== PHASE A: scatter(prev) + gather(cur) + idx prefetch(next) =====
        #pragma unroll
        for (int k = 0; k < 4; k++) {
            int d = dPrev[k];
            if (d >= 0) {
                int e = hgrp + 8 * k;
                float4 ex = *(const float4*)(exA + e * 68 + js);
                float4 dl = *(const float4*)(dlP + e * 68 + js);
                float4 vv = *(const float4*)(g_v + (size_t)sPrev[k] * C + js);
                float4 nv;
                nv.x = ex.x * (vv.x + dl.x);
                nv.y = ex.y * (vv.y + dl.y);
                nv.z = ex.z * (vv.z + dl.z);
                nv.w = ex.w * (vv.w + dl.w);
                RED_V4(g_num + (size_t)d * C + js, nv);
                RED_V4(g_den + (size_t)d * C + js, ex);
            }
        }
        #pragma unroll
        for (int k = 0; k < 4; k++) {
            int e = hgrp + 8 * k;
            int s = seB[it * 32 + e];
            int d = deB[it * 32 + e];
            sPrev[k] = s;
            dPrev[k] = d;
            int dc = d < 0 ? 0 : d;
            uint2 qu = *(const uint2*)(g_hQ1 + (size_t)dc * C + js);
            uint2 ku = *(const uint2*)(g_hK1 + (size_t)s  * C + js);
            float4 p4d = g_pos4[dc];
            float4 p4s = g_pos4[s];
            float dpx = p4d.x - p4s.x, dpy = p4d.y - p4s.y, dpz = p4d.z - p4s.z;
            uint2 ua, up;
            if (d >= 0) {
                __half2 q0 = *(__half2*)&qu.x, q1 = *(__half2*)&qu.y;
                __half2 k0 = *(__half2*)&ku.x, k1 = *(__half2*)&ku.y;
                __half2 a0 = __hmax2(__hadd2(__hsub2(q0, k0), ba1h0), hzero);
                __half2 a1 = __hmax2(__hadd2(__hsub2(q1, k1), ba1h1), hzero);
                ua.x = *(unsigned*)&a0;
                ua.y = *(unsigned*)&a1;
                float r0p = fmaf(dpx, pwx.x, fmaf(dpy, pwy.x, fmaf(dpz, pwz.x, bp1.x)));
                float r1p = fmaf(dpx, pwx.y, fmaf(dpy, pwy.y, fmaf(dpz, pwz.y, bp1.y)));
                float r2p = fmaf(dpx, pwx.z, fmaf(dpy, pwy.z, fmaf(dpz, pwz.z, bp1.z)));
                float r3p = fmaf(dpx, pwx.w, fmaf(dpy, pwy.w, fmaf(dpz, pwz.w, bp1.w)));
                up.x = pack_h2(fmaxf(r0p, 0.f), fmaxf(r1p, 0.f));
                up.y = pack_h2(fmaxf(r2p, 0.f), fmaxf(r3p, 0.f));
            } else {
                ua = make_uint2(0u, 0u);
                up = ua;
            }
            *(uint2*)(hidA16 + e * 72 + js) = ua;
            *(uint2*)(hidP16 + e * 72 + js) = up;
        }
        {
            int nv2 = vt + stride;
            if (nv2 < nvt) {
                int ib = (it ^ 1) * 32;
                if (htid < 32) {
                    int e = (nv2 << 5) + htid;
                    seB[ib + htid] = (e < E) ? src[e] : 0;
                } else if (htid < 64) {
                    int e = (nv2 << 5) + htid - 32;
                    deB[ib + htid - 32] = (e < E) ? dst[e] : -1;
                }
            }
        }
        HBAR(barId);

        // ===== PHASE B: fp16 m16n8k16 MMA (ldmatrix A) + epilogue =====
        float acc[2][4][4];
        #pragma unroll
        for (int s2 = 0; s2 < 2; s2++)
            #pragma unroll
            for (int nt = 0; nt < 4; nt++) {
                acc[s2][nt][0] = bias0[nt];
                acc[s2][nt][1] = bias1[nt];
                acc[s2][nt][2] = bias0[nt];
                acc[s2][nt][3] = bias1[nt];
            }
        #pragma unroll
        for (int kt = 0; kt < 4; kt++) {
            unsigned a0[4], a1[4];
            ldsm_x4(a0[0], a0[1], a0[2], a0[3], aAddr0 + kt * 32);
            ldsm_x4(a1[0], a1[1], a1[2], a1[3], aAddr1 + kt * 32);
            #pragma unroll
            for (int nt = 0; nt < 4; nt++) {
                MMA_F16(acc[0][nt], a0, bB[kt][nt].x, bB[kt][nt].y);
                MMA_F16(acc[1][nt], a1, bB[kt][nt].x, bB[kt][nt].y);
            }
        }
        {
            int rA = lane >> 2;
            int cbv = 2 * (lane & 3);
            #pragma unroll
            for (int s2 = 0; s2 < 2; s2++) {
                int rb = s2 * 16 + rA;
                #pragma unroll
                for (int nt = 0; nt < 4; nt++) {
                    int col = n0b + nt * 8 + cbv;
                    float v0, v1, v2, v3;
                    if (isA) {
                        v0 = __expf(fmaxf(acc[s2][nt][0], 0.f));
                        v1 = __expf(fmaxf(acc[s2][nt][1], 0.f));
                        v2 = __expf(fmaxf(acc[s2][nt][2], 0.f));
                        v3 = __expf(fmaxf(acc[s2][nt][3], 0.f));
                    } else {
                        v0 = fmaxf(acc[s2][nt][0], 0.f);
                        v1 = fmaxf(acc[s2][nt][1], 0.f);
                        v2 = fmaxf(acc[s2][nt][2], 0.f);
                        v3 = fmaxf(acc[s2][nt][3], 0.f);
                    }
                    *(float2*)(res + rb * 68 + col)       = make_float2(v0, v1);
                    *(float2*)(res + (rb + 8) * 68 + col) = make_float2(v2, v3);
                }
            }
        }
        HBAR(barId);
    }

    // ===== pipeline drain: scatter of the final vtile =====
    #pragma unroll
    for (int k = 0; k < 4; k++) {
        int d = dPrev[k];
        if (d >= 0) {
            int e = hgrp + 8 * k;
            float4 ex = *(const float4*)(exA + e * 68 + js);
            float4 dl = *(const float4*)(dlP + e * 68 + js);
            float4 vv = *(const float4*)(g_v + (size_t)sPrev[k] * C + js);
            float4 nv;
            nv.x = ex.x * (vv.x + dl.x);
            nv.y = ex.y * (vv.y + dl.y);
            nv.z = ex.z * (vv.z + dl.z);
            nv.w = ex.w * (vv.w + dl.w);
            RED_V4(g_num + (size_t)d * C + js, nv);
            RED_V4(g_den + (size_t)d * C + js, ex);
        }
    }
}

// ---------------- K3: out kernel — fp16 MMA over 64-node tiles ------------------
__global__ void __launch_bounds__(256)
out_kernel(const float* __restrict__ b_out, float* __restrict__ out, int n)
{
    __shared__ __half rs[64 * 72];
    int tid  = threadIdx.x;
    int lane = tid & 31;
    int wid  = tid >> 5;
    int base = blockIdx.x * 64;

    for (int t = tid; t < 1024; t += 256) {
        int row = t >> 4;
        int col = (t & 15) * 4;
        int node = base + row;
        float4 r = make_float4(0.f, 0.f, 0.f, 0.f);
        if (node < n) {
            float4 nu = *(const float4*)(g_num + (size_t)node * C + col);
            float4 de = *(const float4*)(g_den + (size_t)node * C + col);
            r.x = nu.x / (de.x + 1e-16f);
            r.y = nu.y / (de.y + 1e-16f);
            r.z = nu.z / (de.z + 1e-16f);
            r.w = nu.w / (de.w + 1e-16f);
        }
        uint2 u;
        u.x = pack_h2(r.x, r.y);
        u.y = pack_h2(r.z, r.w);
        *(uint2*)(rs + row * 72 + col) = u;
    }
    __syncthreads();

    int r0 = (wid & 3) * 16;
    int nh = wid >> 2;
    int n0 = nh * 32;
    int rA = lane >> 2;
    int cb = 2 * (lane & 3);
    int rowg0 = base + r0 + rA;
    int rowg1 = rowg0 + 8;

    uint32_t aR = smem_u32(rs) + (uint32_t)(((r0 + (lane & 15)) * 72 + ((lane >> 4) << 3)) * 2);

    float acc[4][4];
    #pragma unroll
    for (int nt = 0; nt < 4; nt++) {
        int col = n0 + nt * 8 + cb;
        float b0 = b_out[col], b1 = b_out[col + 1];
        acc[nt][0] = b0; acc[nt][1] = b1; acc[nt][2] = b0; acc[nt][3] = b1;
    }
    #pragma unroll
    for (int kt = 0; kt < 4; kt++) {
        unsigned a[4];
        ldsm_x4(a[0], a[1], a[2], a[3], aR + kt * 32);
        #pragma unroll
        for (int nt = 0; nt < 4; nt++) {
            uint2 b = g_hWout[(kt * 8 + nh * 4 + nt) * 32 + lane];
            MMA_F16(acc[nt], a, b.x, b.y);
        }
    }
    #pragma unroll
    for (int nt = 0; nt < 4; nt++) {
        int col = n0 + nt * 8 + cb;
        if (rowg0 < n)
            *(float2*)(out + (size_t)rowg0 * C + col) =
                make_float2(fmaxf(acc[nt][0], 0.f), fmaxf(acc[nt][1], 0.f));
        if (rowg1 < n)
            *(float2*)(out + (size_t)rowg1 * C + col) =
                make_float2(fmaxf(acc[nt][2], 0.f), fmaxf(acc[nt][3], 0.f));
    }
}

// ---------------- launch --------------------------------------------------------
extern "C" void kernel_launch(void* const* d_in, const int* in_sizes, int n_in,
                              void* d_out, int out_size)
{
    const float* x      = (const float*)d_in[0];
    const float* pos    = (const float*)d_in[1];
    const int*   ei     = (const int*)  d_in[2];
    const float* W_in   = (const float*)d_in[3];
    const float* b_in   = (const float*)d_in[4];
    const float* W_out  = (const float*)d_in[5];
    const float* b_out  = (const float*)d_in[6];
    const float* W_lin  = (const float*)d_in[7];
    const float* W_src  = (const float*)d_in[8];
    const float* W_dst  = (const float*)d_in[9];
    const float* pos_w1 = (const float*)d_in[10];
    const float* pos_b1 = (const float*)d_in[11];
    const float* pos_w2 = (const float*)d_in[12];
    const float* pos_b2 = (const float*)d_in[13];
    const float* att_w1 = (const float*)d_in[14];
    const float* att_b1 = (const float*)d_in[15];
    const float* att_w2 = (const float*)d_in[16];
    const float* att_b2 = (const float*)d_in[17];

    int n = in_sizes[0] / C;
    int E = in_sizes[2] / 2;
    const int* srcArr = ei;
    const int* dstArr = ei + E;

    size_t smemNode = 35840;
    size_t smemEdge = 54272;   // 2 x 27136
    cudaFuncSetAttribute(node_kernel, cudaFuncAttributeMaxDynamicSharedMemorySize, (int)smemNode);
    cudaFuncSetAttribute(edge_kernel, cudaFuncAttributeMaxDynamicSharedMemorySize, (int)smemEdge);

    int tilesN = (n + 63) / 64;

    prep_kernel<<<1, 256>>>(att_w1, W_dst, W_src, W_in, W_lin, att_w2, pos_w2, W_out,
                            pos_b1, pos_b2);
    node_kernel<<<tilesN, 256, smemNode>>>(x, pos, b_in, att_b1, att_b2, n);
    spacer_kernel<<<1, 32>>>();   // keeps edge_kernel at launch #4 (ncu capture slot)
    edge_kernel<<<444, 256, smemEdge>>>(srcArr, dstArr, att_b1, pos_b1, pos_w1,
                                        att_b2, pos_b2, E);
    out_kernel<<<tilesN, 256>>>(b_out, (float*)d_out, n);
}

// round 16
// speedup vs baseline: 1.1103x; 1.0349x over previous
#include <cuda_runtime.h>
#include <cuda_fp16.h>
#include <cstdint>

#define C 64
#define MAXN 50000
#define MAXE 800000

// ---------------- device scratch (static: no allocation allowed) ----------------
__device__ float  g_v[MAXN * C];
__device__ __half g_hQ1[MAXN * C];
__device__ __half g_hK1[MAXN * C];
__device__ float4 g_pos4[MAXN];
__device__ float  g_num[MAXN * C];
__device__ float  g_den[MAXN * C];
__device__ float g_Mq_t[C * C];
__device__ float g_Mk_t[C * C];
__device__ float g_Win_t[C * C];
__device__ float g_Wlin_t[C * C];
__device__ float g_w2a_t[C * C];
__device__ float g_w2p_t[C * C];
__device__ float g_Wout_t[C * C];
__device__ float g_delta0[C];
// fp16 B fragments (m16n8k16): [(kt*8+nt)*32+lane] -> uint2 {b0,b1}
__device__ uint2 g_hWin[1024];
__device__ uint2 g_hWlin[1024];
__device__ uint2 g_hMq[1024];
__device__ uint2 g_hMk[1024];
__device__ uint2 g_hW2a[1024];
__device__ uint2 g_hW2p[1024];
__device__ uint2 g_hWout[1024];

__device__ __forceinline__ unsigned pack_h2(float a, float b) {
    __half2 h = __floats2half2_rn(a, b);
    return *reinterpret_cast<unsigned*>(&h);
}

#define MMA_F16(d, a, b0, b1)                                                \
    asm volatile("mma.sync.aligned.m16n8k16.row.col.f32.f16.f16.f32 "        \
                 "{%0,%1,%2,%3}, {%4,%5,%6,%7}, {%8,%9}, {%0,%1,%2,%3};"     \
                 : "+f"(d[0]), "+f"(d[1]), "+f"(d[2]), "+f"(d[3])            \
                 : "r"(a[0]), "r"(a[1]), "r"(a[2]), "r"(a[3]),               \
                   "r"(b0), "r"(b1))

#define RED_V4(ptr, v)                                                       \
    asm volatile("red.global.add.v4.f32 [%0], {%1,%2,%3,%4};"                \
                 :: "l"(ptr), "f"((v).x), "f"((v).y), "f"((v).z), "f"((v).w) \
                 : "memory")

#define HBAR(id)                                                             \
    asm volatile("bar.sync %0, 128;" :: "r"(id) : "memory")

__device__ __forceinline__ void ldsm_x4(unsigned& r0, unsigned& r1,
                                        unsigned& r2, unsigned& r3, unsigned addr) {
    asm volatile("ldmatrix.sync.aligned.m8n8.x4.shared.b16 {%0,%1,%2,%3}, [%4];"
                 : "=r"(r0), "=r"(r1), "=r"(r2), "=r"(r3) : "r"(addr));
}

__device__ __forceinline__ uint32_t smem_u32(const void* p) {
    uint32_t r;
    asm("{ .reg .u64 t; cvta.to.shared.u64 t, %1; cvt.u32.u64 %0, t; }"
        : "=r"(r) : "l"(p));
    return r;
}

// ---------------- K0: weight prep ------------------------------------------------
__global__ void prep_kernel(const float* __restrict__ att_w1,
                            const float* __restrict__ W_dst,
                            const float* __restrict__ W_src,
                            const float* __restrict__ W_in,
                            const float* __restrict__ W_lin,
                            const float* __restrict__ att_w2,
                            const float* __restrict__ pos_w2,
                            const float* __restrict__ W_out,
                            const float* __restrict__ pos_b1,
                            const float* __restrict__ pos_b2)
{
    __shared__ float s_a[C * C];
    __shared__ float s_d[C * C];
    __shared__ float s_s[C * C];
    int tid = threadIdx.x;
    for (int t = tid; t < C * C; t += blockDim.x) {
        s_a[t] = att_w1[t];
        s_d[t] = W_dst[t];
        s_s[t] = W_src[t];
    }
    __syncthreads();
    for (int idx = tid; idx < C * C; idx += blockDim.x) {
        int t = idx >> 6, j = idx & 63;
        float aq = 0.f, ak = 0.f;
        #pragma unroll 8
        for (int u = 0; u < C; u++) {
            float a = s_a[t * C + u];
            aq = fmaf(a, s_d[u * C + j], aq);
            ak = fmaf(a, s_s[u * C + j], ak);
        }
        g_Mq_t[j * C + t] = aq;
        g_Mk_t[j * C + t] = ak;
    }
    for (int idx = tid; idx < C * C; idx += blockDim.x) {
        int cc = idx >> 6, j = idx & 63;
        g_Win_t[j * C + cc]  = W_in[idx];
        g_Wlin_t[j * C + cc] = W_lin[idx];
        g_w2a_t[j * C + cc]  = att_w2[idx];
        g_w2p_t[j * C + cc]  = pos_w2[idx];
        g_Wout_t[j * C + cc] = W_out[idx];
    }
    if (tid < C) {
        float acc = pos_b2[tid];
        #pragma unroll 8
        for (int j = 0; j < C; j++)
            acc = fmaf(fmaxf(pos_b1[j], 0.f), pos_w2[tid * C + j], acc);
        g_delta0[tid] = fmaxf(acc, 0.f);
    }
    __syncthreads();
    for (int t = tid; t < 1024; t += blockDim.x) {
        int kt   = t >> 8;
        int nt   = (t >> 5) & 7;
        int lane = t & 31;
        int tig = lane & 3, gid = lane >> 2;
        int n  = nt * 8 + gid;
        int k0 = kt * 16 + tig * 2;
        #define BUILD(dst, srcm)                                             \
            { uint2 u;                                                        \
              u.x = pack_h2(srcm[k0 * 64 + n],       srcm[(k0 + 1) * 64 + n]);\
              u.y = pack_h2(srcm[(k0 + 8) * 64 + n], srcm[(k0 + 9) * 64 + n]);\
              dst[t] = u; }
        BUILD(g_hWin,  g_Win_t)
        BUILD(g_hWlin, g_Wlin_t)
        BUILD(g_hMq,   g_Mq_t)
        BUILD(g_hMk,   g_Mk_t)
        BUILD(g_hW2a,  g_w2a_t)
        BUILD(g_hW2p,  g_w2p_t)
        BUILD(g_hWout, g_Wout_t)
        #undef BUILD
    }
}

// ---------------- K1: node kernel — fp16 MMA, v kept in registers ---------------
// smem: xs half[64*72] @0 (9216B), hs half[64*72] @9216   (total 18432B)
__global__ void __launch_bounds__(256)
node_kernel(const float* __restrict__ x,
            const float* __restrict__ pos,
            const float* __restrict__ b_in,
            const float* __restrict__ att_b1,
            const float* __restrict__ att_b2,
            int n)
{
    extern __shared__ char smN[];
    __half* xs = (__half*)smN;
    __half* hs = (__half*)(smN + 9216);
    int tid  = threadIdx.x;
    int lane = tid & 31;
    int wid  = tid >> 5;
    int base = blockIdx.x * 64;

    for (int t = tid; t < 1024; t += 256) {
        int row = t >> 4;
        int col = (t & 15) * 4;
        int node = base + row;
        float4 v4 = make_float4(0.f, 0.f, 0.f, 0.f);
        if (node < n) v4 = *(const float4*)(x + (size_t)node * C + col);
        uint2 u;
        u.x = pack_h2(v4.x, v4.y);
        u.y = pack_h2(v4.z, v4.w);
        *(uint2*)(xs + row * 72 + col) = u;
    }
    if (tid < 64) {
        int node = base + tid;
        if (node < n) {
            g_pos4[node] = make_float4(pos[(size_t)node * 3 + 0],
                                       pos[(size_t)node * 3 + 1],
                                       pos[(size_t)node * 3 + 2], 0.f);
        }
    }
    __syncthreads();

    int r0 = (wid & 3) * 16;
    int nh = wid >> 2;
    int n0 = nh * 32;
    int rA = lane >> 2;
    int cb = 2 * (lane & 3);
    int rowg0 = base + r0 + rA;
    int rowg1 = rowg0 + 8;
    bool ok0 = rowg0 < n, ok1 = rowg1 < n;

    uint32_t aX = smem_u32(xs) + (uint32_t)(((r0 + (lane & 15)) * 72 + ((lane >> 4) << 3)) * 2);
    uint32_t aH = smem_u32(hs) + (uint32_t)(((r0 + (lane & 15)) * 72 + ((lane >> 4) << 3)) * 2);

    // ---- GEMM1: h = relu(x @ Win^T + b_in) -> hs (fp16) ----
    {
        float acc[4][4];
        #pragma unroll
        for (int nt = 0; nt < 4; nt++) {
            int col = n0 + nt * 8 + cb;
            float b0 = b_in[col], b1 = b_in[col + 1];
            acc[nt][0] = b0; acc[nt][1] = b1; acc[nt][2] = b0; acc[nt][3] = b1;
        }
        #pragma unroll
        for (int kt = 0; kt < 4; kt++) {
            unsigned a[4];
            ldsm_x4(a[0], a[1], a[2], a[3], aX + kt * 32);
            #pragma unroll
            for (int nt = 0; nt < 4; nt++) {
                uint2 b = g_hWin[(kt * 8 + nh * 4 + nt) * 32 + lane];
                MMA_F16(acc[nt], a, b.x, b.y);
            }
        }
        #pragma unroll
        for (int nt = 0; nt < 4; nt++) {
            int col = n0 + nt * 8 + cb;
            *(unsigned*)(hs + (r0 + rA) * 72 + col) =
                pack_h2(fmaxf(acc[nt][0], 0.f), fmaxf(acc[nt][1], 0.f));
            *(unsigned*)(hs + (r0 + 8 + rA) * 72 + col) =
                pack_h2(fmaxf(acc[nt][2], 0.f), fmaxf(acc[nt][3], 0.f));
        }
    }
    __syncthreads();

    // ---- GEMM2 fused: v = h@Wlin^T (kept in regs), q = h@Mq^T, k = h@Mk^T ----
    float av[4][4];
    {
        float aq[4][4], ak[4][4];
        #pragma unroll
        for (int nt = 0; nt < 4; nt++)
            #pragma unroll
            for (int q = 0; q < 4; q++) { av[nt][q] = 0.f; aq[nt][q] = 0.f; ak[nt][q] = 0.f; }
        #pragma unroll
        for (int kt = 0; kt < 4; kt++) {
            unsigned a[4];
            ldsm_x4(a[0], a[1], a[2], a[3], aH + kt * 32);
            #pragma unroll
            for (int nt = 0; nt < 4; nt++) {
                int fi = (kt * 8 + nh * 4 + nt) * 32 + lane;
                uint2 bv = g_hWlin[fi];
                uint2 bq = g_hMq[fi];
                uint2 bk = g_hMk[fi];
                MMA_F16(av[nt], a, bv.x, bv.y);
                MMA_F16(aq[nt], a, bq.x, bq.y);
                MMA_F16(ak[nt], a, bk.x, bk.y);
            }
        }
        #pragma unroll
        for (int nt = 0; nt < 4; nt++) {
            int col = n0 + nt * 8 + cb;
            if (ok0) *(float2*)(g_v + (size_t)rowg0 * C + col) = make_float2(av[nt][0], av[nt][1]);
            if (ok1) *(float2*)(g_v + (size_t)rowg1 * C + col) = make_float2(av[nt][2], av[nt][3]);
            float ba0 = att_b1[col], ba1 = att_b1[col + 1];
            *(unsigned*)(xs + (r0 + rA) * 72 + col) =
                pack_h2(fmaxf(aq[nt][0] - ak[nt][0] + ba0, 0.f),
                        fmaxf(aq[nt][1] - ak[nt][1] + ba1, 0.f));
            *(unsigned*)(xs + (r0 + 8 + rA) * 72 + col) =
                pack_h2(fmaxf(aq[nt][2] - ak[nt][2] + ba0, 0.f),
                        fmaxf(aq[nt][3] - ak[nt][3] + ba1, 0.f));
            if (ok0) {
                *(__half2*)(g_hQ1 + (size_t)rowg0 * C + col) = __floats2half2_rn(aq[nt][0], aq[nt][1]);
                *(__half2*)(g_hK1 + (size_t)rowg0 * C + col) = __floats2half2_rn(ak[nt][0], ak[nt][1]);
            }
            if (ok1) {
                *(__half2*)(g_hQ1 + (size_t)rowg1 * C + col) = __floats2half2_rn(aq[nt][2], aq[nt][3]);
                *(__half2*)(g_hK1 + (size_t)rowg1 * C + col) = __floats2half2_rn(ak[nt][2], ak[nt][3]);
            }
        }
    }
    __syncthreads();

    // ---- GEMM3: s = a @ W2a^T + b2; e = exp(relu(s)); init num/den (uses av) ----
    {
        float acc[4][4];
        #pragma unroll
        for (int nt = 0; nt < 4; nt++) {
            int col = n0 + nt * 8 + cb;
            float b0 = att_b2[col], b1 = att_b2[col + 1];
            acc[nt][0] = b0; acc[nt][1] = b1; acc[nt][2] = b0; acc[nt][3] = b1;
        }
        #pragma unroll
        for (int kt = 0; kt < 4; kt++) {
            unsigned a[4];
            ldsm_x4(a[0], a[1], a[2], a[3], aX + kt * 32);
            #pragma unroll
            for (int nt = 0; nt < 4; nt++) {
                uint2 b = g_hW2a[(kt * 8 + nh * 4 + nt) * 32 + lane];
                MMA_F16(acc[nt], a, b.x, b.y);
            }
        }
        #pragma unroll
        for (int nt = 0; nt < 4; nt++) {
            int col = n0 + nt * 8 + cb;
            float d0 = g_delta0[col], d1 = g_delta0[col + 1];
            float e0 = __expf(fmaxf(acc[nt][0], 0.f));
            float e1 = __expf(fmaxf(acc[nt][1], 0.f));
            float e2 = __expf(fmaxf(acc[nt][2], 0.f));
            float e3 = __expf(fmaxf(acc[nt][3], 0.f));
            if (ok0) {
                *(float2*)(g_den + (size_t)rowg0 * C + col) = make_float2(e0, e1);
                *(float2*)(g_num + (size_t)rowg0 * C + col) =
                    make_float2(e0 * (av[nt][0] + d0), e1 * (av[nt][1] + d1));
            }
            if (ok1) {
                *(float2*)(g_den + (size_t)rowg1 * C + col) = make_float2(e2, e3);
                *(float2*)(g_num + (size_t)rowg1 * C + col) =
                    make_float2(e2 * (av[nt][2] + d0), e3 * (av[nt][3] + d1));
            }
        }
    }
}

// ---------------- K2: edge kernel — R13 champion (half-pipelines) ---------------
// Per-half smem (offset h*27136 bytes):
//   [0, 4608)      hidA16  32 rows x 72 halves
//   [4608, 9216)   hidP16
//   [9216, 17920)  exA     32 x 68 fp32
//   [17920, 26624) dlP
//   [26624, 26880) seB [2][32]
//   [26880, 27136) deB [2][32]
__global__ void __launch_bounds__(256, 3)
edge_kernel(const int* __restrict__ src, const int* __restrict__ dst,
            const float* __restrict__ att_b1, const float* __restrict__ pos_b1,
            const float* __restrict__ pos_w1,
            const float* __restrict__ att_b2, const float* __restrict__ pos_b2,
            int E)
{
    extern __shared__ char smE[];
    int tid  = threadIdx.x;
    int lane = tid & 31;
    int wid  = tid >> 5;
    bool isA = (wid < 4);
    int sub  = wid & 3;
    int h    = sub >> 1;
    int nhE  = sub & 1;
    int n0b  = nhE * 32;

    char* hb = smE + h * 27136;
    __half* hidA16 = (__half*)hb;
    __half* hidP16 = (__half*)(hb + 4608);
    float*  exA    = (float*)(hb + 9216);
    float*  dlP    = (float*)(hb + 17920);
    int*    seB    = (int*)(hb + 26624);
    int*    deB    = (int*)(hb + 26880);

    const float* b2 = isA ? att_b2 : pos_b2;
    __half* hid = isA ? hidA16 : hidP16;
    float*  res = isA ? exA    : dlP;

    uint2 bB[4][4];
    {
        const uint2* hw2 = isA ? g_hW2a : g_hW2p;
        #pragma unroll
        for (int kt = 0; kt < 4; kt++)
            #pragma unroll
            for (int nt = 0; nt < 4; nt++)
                bB[kt][nt] = hw2[((kt * 8) + nhE * 4 + nt) * 32 + lane];
    }
    float bias0[4], bias1[4];
    #pragma unroll
    for (int nt = 0; nt < 4; nt++) {
        int col = n0b + nt * 8 + 2 * (lane & 3);
        bias0[nt] = b2[col];
        bias1[nt] = b2[col + 1];
    }

    int hwi  = (wid & 1) | ((wid >> 2) << 1);
    int htid = hwi * 32 + lane;
    int hgrp = htid >> 4;
    int js   = (htid & 15) << 2;

    float4 ba1 = *(const float4*)(att_b1 + js);
    __half2 ba1h0 = __floats2half2_rn(ba1.x, ba1.y);
    __half2 ba1h1 = __floats2half2_rn(ba1.z, ba1.w);
    __half2 hzero = __floats2half2_rn(0.f, 0.f);
    float4 bp1 = *(const float4*)(pos_b1 + js);
    float4 pwx, pwy, pwz;
    {
        float3 w0 = *(const float3*)(pos_w1 + (js + 0) * 3);
        float3 w1 = *(const float3*)(pos_w1 + (js + 1) * 3);
        float3 w2 = *(const float3*)(pos_w1 + (js + 2) * 3);
        float3 w3 = *(const float3*)(pos_w1 + (js + 3) * 3);
        pwx = make_float4(w0.x, w1.x, w2.x, w3.x);
        pwy = make_float4(w0.y, w1.y, w2.y, w3.y);
        pwz = make_float4(w0.z, w1.z, w2.z, w3.z);
    }

    uint32_t hidBase = smem_u32(hid);
    uint32_t aAddr0 = hidBase + (uint32_t)((((lane & 15)) * 72 + ((lane >> 4) << 3)) * 2);
    uint32_t aAddr1 = hidBase + (uint32_t)(((16 + (lane & 15)) * 72 + ((lane >> 4) << 3)) * 2);

    int sPrev[4], dPrev[4];
    #pragma unroll
    for (int k = 0; k < 4; k++) dPrev[k] = -1;

    int nvt    = (E + 31) >> 5;
    int H      = blockIdx.x * 2 + h;
    int stride = gridDim.x * 2;
    int barId  = h + 1;

    if (H < nvt) {
        if (htid < 32) {
            int e = (H << 5) + htid;
            seB[htid] = (e < E) ? src[e] : 0;
        } else if (htid < 64) {
            int e = (H << 5) + htid - 32;
            deB[htid - 32] = (e < E) ? dst[e] : -1;
        }
    }
    __syncthreads();

    int it = 0;
    for (int vt = H; vt < nvt; vt += stride, it ^= 1) {
        // ===== PHASE A: scatter(prev) + gather(cur) + idx prefetch(next) =====
        #pragma unroll
        for (int k = 0; k < 4; k++) {
            int d = dPrev[k];
            if (d >= 0) {
                int e = hgrp + 8 * k;
                float4 ex = *(const float4*)(exA + e * 68 + js);
                float4 dl = *(const float4*)(dlP + e * 68 + js);
                float4 vv = *(const float4*)(g_v + (size_t)sPrev[k] * C + js);
                float4 nv;
                nv.x = ex.x * (vv.x + dl.x);
                nv.y = ex.y * (vv.y + dl.y);
                nv.z = ex.z * (vv.z + dl.z);
                nv.w = ex.w * (vv.w + dl.w);
                RED_V4(g_num + (size_t)d * C + js, nv);
                RED_V4(g_den + (size_t)d * C + js, ex);
            }
        }
        #pragma unroll
        for (int k = 0; k < 4; k++) {
            int e = hgrp + 8 * k;
            int s = seB[it * 32 + e];
            int d = deB[it * 32 + e];
            sPrev[k] = s;
            dPrev[k] = d;
            int dc = d < 0 ? 0 : d;
            uint2 qu = *(const uint2*)(g_hQ1 + (size_t)dc * C + js);
            uint2 ku = *(const uint2*)(g_hK1 + (size_t)s  * C + js);
            float4 p4d = g_pos4[dc];
            float4 p4s = g_pos4[s];
            float dpx = p4d.x - p4s.x, dpy = p4d.y - p4s.y, dpz = p4d.z - p4s.z;
            uint2 ua, up;
            if (d >= 0) {
                __half2 q0 = *(__half2*)&qu.x, q1 = *(__half2*)&qu.y;
                __half2 k0 = *(__half2*)&ku.x, k1 = *(__half2*)&ku.y;
                __half2 a0 = __hmax2(__hadd2(__hsub2(q0, k0), ba1h0), hzero);
                __half2 a1 = __hmax2(__hadd2(__hsub2(q1, k1), ba1h1), hzero);
                ua.x = *(unsigned*)&a0;
                ua.y = *(unsigned*)&a1;
                float r0p = fmaf(dpx, pwx.x, fmaf(dpy, pwy.x, fmaf(dpz, pwz.x, bp1.x)));
                float r1p = fmaf(dpx, pwx.y, fmaf(dpy, pwy.y, fmaf(dpz, pwz.y, bp1.y)));
                float r2p = fmaf(dpx, pwx.z, fmaf(dpy, pwy.z, fmaf(dpz, pwz.z, bp1.z)));
                float r3p = fmaf(dpx, pwx.w, fmaf(dpy, pwy.w, fmaf(dpz, pwz.w, bp1.w)));
                up.x = pack_h2(fmaxf(r0p, 0.f), fmaxf(r1p, 0.f));
                up.y = pack_h2(fmaxf(r2p, 0.f), fmaxf(r3p, 0.f));
            } else {
                ua = make_uint2(0u, 0u);
                up = ua;
            }
            *(uint2*)(hidA16 + e * 72 + js) = ua;
            *(uint2*)(hidP16 + e * 72 + js) = up;
        }
        {
            int nv2 = vt + stride;
            if (nv2 < nvt) {
                int ib = (it ^ 1) * 32;
                if (htid < 32) {
                    int e = (nv2 << 5) + htid;
                    seB[ib + htid] = (e < E) ? src[e] : 0;
                } else if (htid < 64) {
                    int e = (nv2 << 5) + htid - 32;
                    deB[ib + htid - 32] = (e < E) ? dst[e] : -1;
                }
            }
        }
        HBAR(barId);

        // ===== PHASE B: fp16 m16n8k16 MMA (ldmatrix A) + epilogue =====
        float acc[2][4][4];
        #pragma unroll
        for (int s2 = 0; s2 < 2; s2++)
            #pragma unroll
            for (int nt = 0; nt < 4; nt++) {
                acc[s2][nt][0] = bias0[nt];
                acc[s2][nt][1] = bias1[nt];
                acc[s2][nt][2] = bias0[nt];
                acc[s2][nt][3] = bias1[nt];
            }
        #pragma unroll
        for (int kt = 0; kt < 4; kt++) {
            unsigned a0[4], a1[4];
            ldsm_x4(a0[0], a0[1], a0[2], a0[3], aAddr0 + kt * 32);
            ldsm_x4(a1[0], a1[1], a1[2], a1[3], aAddr1 + kt * 32);
            #pragma unroll
            for (int nt = 0; nt < 4; nt++) {
                MMA_F16(acc[0][nt], a0, bB[kt][nt].x, bB[kt][nt].y);
                MMA_F16(acc[1][nt], a1, bB[kt][nt].x, bB[kt][nt].y);
            }
        }
        {
            int rA = lane >> 2;
            int cbv = 2 * (lane & 3);
            #pragma unroll
            for (int s2 = 0; s2 < 2; s2++) {
                int rb = s2 * 16 + rA;
                #pragma unroll
                for (int nt = 0; nt < 4; nt++) {
                    int col = n0b + nt * 8 + cbv;
                    float v0, v1, v2, v3;
                    if (isA) {
                        v0 = __expf(fmaxf(acc[s2][nt][0], 0.f));
                        v1 = __expf(fmaxf(acc[s2][nt][1], 0.f));
                        v2 = __expf(fmaxf(acc[s2][nt][2], 0.f));
                        v3 = __expf(fmaxf(acc[s2][nt][3], 0.f));
                    } else {
                        v0 = fmaxf(acc[s2][nt][0], 0.f);
                        v1 = fmaxf(acc[s2][nt][1], 0.f);
                        v2 = fmaxf(acc[s2][nt][2], 0.f);
                        v3 = fmaxf(acc[s2][nt][3], 0.f);
                    }
                    *(float2*)(res + rb * 68 + col)       = make_float2(v0, v1);
                    *(float2*)(res + (rb + 8) * 68 + col) = make_float2(v2, v3);
                }
            }
        }
        HBAR(barId);
    }

    // ===== pipeline drain: scatter of the final vtile =====
    #pragma unroll
    for (int k = 0; k < 4; k++) {
        int d = dPrev[k];
        if (d >= 0) {
            int e = hgrp + 8 * k;
            float4 ex = *(const float4*)(exA + e * 68 + js);
            float4 dl = *(const float4*)(dlP + e * 68 + js);
            float4 vv = *(const float4*)(g_v + (size_t)sPrev[k] * C + js);
            float4 nv;
            nv.x = ex.x * (vv.x + dl.x);
            nv.y = ex.y * (vv.y + dl.y);
            nv.z = ex.z * (vv.z + dl.z);
            nv.w = ex.w * (vv.w + dl.w);
            RED_V4(g_num + (size_t)d * C + js, nv);
            RED_V4(g_den + (size_t)d * C + js, ex);
        }
    }
}

// ---------------- K3: out kernel — fp16 MMA over 64-node tiles ------------------
__global__ void __launch_bounds__(256)
out_kernel(const float* __restrict__ b_out, float* __restrict__ out, int n)
{
    __shared__ __half rs[64 * 72];
    int tid  = threadIdx.x;
    int lane = tid & 31;
    int wid  = tid >> 5;
    int base = blockIdx.x * 64;

    for (int t = tid; t < 1024; t += 256) {
        int row = t >> 4;
        int col = (t & 15) * 4;
        int node = base + row;
        float4 r = make_float4(0.f, 0.f, 0.f, 0.f);
        if (node < n) {
            float4 nu = *(const float4*)(g_num + (size_t)node * C + col);
            float4 de = *(const float4*)(g_den + (size_t)node * C + col);
            r.x = nu.x / (de.x + 1e-16f);
            r.y = nu.y / (de.y + 1e-16f);
            r.z = nu.z / (de.z + 1e-16f);
            r.w = nu.w / (de.w + 1e-16f);
        }
        uint2 u;
        u.x = pack_h2(r.x, r.y);
        u.y = pack_h2(r.z, r.w);
        *(uint2*)(rs + row * 72 + col) = u;
    }
    __syncthreads();

    int r0 = (wid & 3) * 16;
    int nh = wid >> 2;
    int n0 = nh * 32;
    int rA = lane >> 2;
    int cb = 2 * (lane & 3);
    int rowg0 = base + r0 + rA;
    int rowg1 = rowg0 + 8;

    uint32_t aR = smem_u32(rs) + (uint32_t)(((r0 + (lane & 15)) * 72 + ((lane >> 4) << 3)) * 2);

    float acc[4][4];
    #pragma unroll
    for (int nt = 0; nt < 4; nt++) {
        int col = n0 + nt * 8 + cb;
        float b0 = b_out[col], b1 = b_out[col + 1];
        acc[nt][0] = b0; acc[nt][1] = b1; acc[nt][2] = b0; acc[nt][3] = b1;
    }
    #pragma unroll
    for (int kt = 0; kt < 4; kt++) {
        unsigned a[4];
        ldsm_x4(a[0], a[1], a[2], a[3], aR + kt * 32);
        #pragma unroll
        for (int nt = 0; nt < 4; nt++) {
            uint2 b = g_hWout[(kt * 8 + nh * 4 + nt) * 32 + lane];
            MMA_F16(acc[nt], a, b.x, b.y);
        }
    }
    #pragma unroll
    for (int nt = 0; nt < 4; nt++) {
        int col = n0 + nt * 8 + cb;
        if (rowg0 < n)
            *(float2*)(out + (size_t)rowg0 * C + col) =
                make_float2(fmaxf(acc[nt][0], 0.f), fmaxf(acc[nt][1], 0.f));
        if (rowg1 < n)
            *(float2*)(out + (size_t)rowg1 * C + col) =
                make_float2(fmaxf(acc[nt][2], 0.f), fmaxf(acc[nt][3], 0.f));
    }
}

// ---------------- launch --------------------------------------------------------
extern "C" void kernel_launch(void* const* d_in, const int* in_sizes, int n_in,
                              void* d_out, int out_size)
{
    const float* x      = (const float*)d_in[0];
    const float* pos    = (const float*)d_in[1];
    const int*   ei     = (const int*)  d_in[2];
    const float* W_in   = (const float*)d_in[3];
    const float* b_in   = (const float*)d_in[4];
    const float* W_out  = (const float*)d_in[5];
    const float* b_out  = (const float*)d_in[6];
    const float* W_lin  = (const float*)d_in[7];
    const float* W_src  = (const float*)d_in[8];
    const float* W_dst  = (const float*)d_in[9];
    const float* pos_w1 = (const float*)d_in[10];
    const float* pos_b1 = (const float*)d_in[11];
    const float* pos_w2 = (const float*)d_in[12];
    const float* pos_b2 = (const float*)d_in[13];
    const float* att_w1 = (const float*)d_in[14];
    const float* att_b1 = (const float*)d_in[15];
    const float* att_w2 = (const float*)d_in[16];
    const float* att_b2 = (const float*)d_in[17];

    int n = in_sizes[0] / C;
    int E = in_sizes[2] / 2;
    const int* srcArr = ei;
    const int* dstArr = ei + E;

    size_t smemNode = 18432;
    size_t smemEdge = 54272;   // 2 x 27136
    cudaFuncSetAttribute(node_kernel, cudaFuncAttributeMaxDynamicSharedMemorySize, (int)smemNode);
    cudaFuncSetAttribute(edge_kernel, cudaFuncAttributeMaxDynamicSharedMemorySize, (int)smemEdge);

    int tilesN = (n + 63) / 64;

    prep_kernel<<<1, 256>>>(att_w1, W_dst, W_src, W_in, W_lin, att_w2, pos_w2, W_out,
                            pos_b1, pos_b2);
    node_kernel<<<tilesN, 256, smemNode>>>(x, pos, b_in, att_b1, att_b2, n);
    edge_kernel<<<444, 256, smemEdge>>>(srcArr, dstArr, att_b1, pos_b1, pos_w1,
                                        att_b2, pos_b2, E);
    out_kernel<<<tilesN, 256>>>(b_out, (float*)d_out, n);
}